// round 8
// baseline (speedup 1.0000x reference)
#include <cuda_runtime.h>
#include <cuda_fp16.h>
#include <cstdint>
#include <math_constants.h>

// Fixed dataset shape: N=50000, E=800000, Fin=128, H=C=64
#define NMAX 50048
#define EMAX 800000
#define HC   64

// ---------------- scratch (__device__ globals; no allocation allowed) --------------
__device__ __half2 g_h2[NMAX * 32];   // h = x @ W, fp16x2 (channel pairs)
__device__ float   g_x2[NMAX * HC];   // layer-2 input (fp32)
__device__ float   g_as[NMAX];        // alpha_src per node
__device__ float   g_ad[NMAX];        // alpha_dst per node
__device__ int     g_src[EMAX];       // edge src
__device__ int     g_dst[EMAX];       // edge dst
__device__ int     g_rank[EMAX];      // rank of edge within its dst row
__device__ int     g_deg[NMAX];       // in-degree histogram
__device__ int     g_row[NMAX + 4];   // CSR row starts (int4-padded)
__device__ int     g_ssrc[EMAX];      // src ids grouped by dst

// packed f32x2 fma (sm_103a; ptxas never emits FFMA2 from C++)
__device__ __forceinline__ void fma2(unsigned long long& acc,
                                     unsigned long long x2, unsigned long long w2) {
    asm("fma.rn.f32x2 %0, %1, %2, %0;" : "+l"(acc) : "l"(x2), "l"(w2));
}

// ---------------- ingest: dtype-detect + convert + histogram + rank -----------------
__global__ void k_zero() {
    int i = blockIdx.x * 256 + threadIdx.x;
    if (i < NMAX / 4) ((int4*)g_deg)[i] = make_int4(0, 0, 0, 0);
}

// 2 edges/thread. Dtype vote: read edge pair AS longlong2 (spans exactly the int32
// buffer bytes — safe both ways). int64 data: every value in [0,N) -> block votes
// int64. int32 data: each ll combines two adjacent int32s -> essentially never all
// in range for a whole block.
__global__ void k_ingest(const void* __restrict__ eiv, int E, int N) {
    int i = blockIdx.x * 256 + threadIdx.x;
    int e0 = i * 2;
    long long v0 = 0, v1 = 0;
    int ok = 1;
    if (e0 + 1 < E) {
        longlong2 v = ((const longlong2*)eiv)[i];
        v0 = v.x; v1 = v.y;
        ok = (v0 >= 0 && v0 < (long long)N && v1 >= 0 && v1 < (long long)N) ? 1 : 0;
    } else if (e0 < E) {
        v0 = ((const long long*)eiv)[e0];
        ok = (v0 >= 0 && v0 < (long long)N) ? 1 : 0;
    }
    int all64 = __syncthreads_and(ok);
    if (e0 >= E) return;
    int s0, s1 = 0, d0, d1 = 0;
    int has1 = (e0 + 1 < E);
    if (all64) {
        const long long* e = (const long long*)eiv;
        s0 = (int)v0;
        d0 = (int)e[E + e0];
        if (has1) { s1 = (int)v1; d1 = (int)e[E + e0 + 1]; }
    } else {
        const int* e = (const int*)eiv;
        s0 = e[e0];
        d0 = e[E + e0];
        if (has1) { s1 = e[e0 + 1]; d1 = e[E + e0 + 1]; }
    }
    s0 = min(max(s0, 0), N - 1); d0 = min(max(d0, 0), N - 1);
    g_src[e0] = s0; g_dst[e0] = d0;
    g_rank[e0] = atomicAdd(&g_deg[d0], 1);
    if (has1) {
        s1 = min(max(s1, 0), N - 1); d1 = min(max(d1, 0), N - 1);
        g_src[e0 + 1] = s1; g_dst[e0 + 1] = d1;
        g_rank[e0 + 1] = atomicAdd(&g_deg[d1], 1);
    }
}

// single-block exclusive scan over g_deg -> g_row; int4, 4096 elems/iteration
__global__ void k_scan() {
    __shared__ int warp_red[32];
    __shared__ int s_carry;
    int tid = threadIdx.x, lane = tid & 31, wid = tid >> 5;
    if (tid == 0) s_carry = 0;
    __syncthreads();
    const int4* deg4 = (const int4*)g_deg;
    int4*       row4 = (int4*)g_row;
    const int total4 = NMAX / 4;
    for (int base = 0; base < total4; base += 1024) {
        int idx = base + tid;
        int4 v = (idx < total4) ? deg4[idx] : make_int4(0, 0, 0, 0);
        int s = v.x + v.y + v.z + v.w;
        int x = s;
#pragma unroll
        for (int o = 1; o < 32; o <<= 1) {
            int t = __shfl_up_sync(0xFFFFFFFFu, x, o);
            if (lane >= o) x += t;
        }
        if (lane == 31) warp_red[wid] = x;
        __syncthreads();
        if (wid == 0) {
            int w = warp_red[lane];
#pragma unroll
            for (int o = 1; o < 32; o <<= 1) {
                int t = __shfl_up_sync(0xFFFFFFFFu, w, o);
                if (lane >= o) w += t;
            }
            warp_red[lane] = w;
        }
        __syncthreads();
        int wsum = (wid > 0) ? warp_red[wid - 1] : 0;
        int incl = x + wsum;
        int carry = s_carry;
        if (idx < total4) {
            int e0 = carry + incl - s;
            int4 r;
            r.x = e0;
            r.y = e0 + v.x;
            r.z = e0 + v.x + v.y;
            r.w = e0 + v.x + v.y + v.z;
            row4[idx] = r;
        }
        __syncthreads();
        if (tid == 1023) s_carry = carry + incl;
        __syncthreads();
    }
}

// atomic-free scatter, 4 edges/thread (int4 loads; MLP=4 on gathers/scatters)
__global__ void k_scatter(int E) {
    int i = blockIdx.x * 256 + threadIdx.x;
    int nvec = E >> 2;
    if (i < nvec) {
        int4 d = ((const int4*)g_dst)[i];
        int4 r = ((const int4*)g_rank)[i];
        int4 s = ((const int4*)g_src)[i];
        int b0 = g_row[d.x], b1 = g_row[d.y], b2 = g_row[d.z], b3 = g_row[d.w];
        g_ssrc[b0 + r.x] = s.x;
        g_ssrc[b1 + r.y] = s.y;
        g_ssrc[b2 + r.z] = s.z;
        g_ssrc[b3 + r.w] = s.w;
    } else if (i == nvec) {          // tail (E % 4 edges)
        for (int e = nvec * 4; e < E; e++)
            g_ssrc[g_row[g_dst[e]] + g_rank[e]] = g_src[e];
    }
}

// ---------------- GEMM (FFMA2) + fused alpha + fp16 h store -------------------------
// H[N,64] = X[N,K] @ W[K,64]; 16 rows/block, 256 threads (64 cols x 4 row-groups).
template <int K>
__launch_bounds__(256)
__global__ void k_gemm64(const float* __restrict__ X, const float* __restrict__ W,
                         const float* __restrict__ avs, const float* __restrict__ avd,
                         int N) {
    __shared__ float Ws[K * 64];
    __shared__ float Xs[K * 16];         // transposed: Xs[k*16 + r], float4-aligned
    __shared__ float red[8][4][2];       // [warp][row-in-group][src/dst]
    int tid = threadIdx.x;
    for (int i = tid; i < K * 64; i += 256) Ws[i] = W[i];
    int row0 = blockIdx.x * 16;
    for (int i = tid; i < K * 16; i += 256) {
        int r = i / K, k = i - r * K;
        int row = row0 + r;
        Xs[k * 16 + r] = (row < N) ? X[row * K + k] : 0.f;
    }
    __syncthreads();
    int c = tid & 63, g = tid >> 6, wid = tid >> 5, lane = tid & 31;
    unsigned long long acc01 = 0ull, acc23 = 0ull;   // packed f32x2 accumulators
#pragma unroll 16
    for (int k = 0; k < K; k++) {
        float w = Ws[k * 64 + c];
        unsigned long long w2;
        asm("mov.b64 %0, {%1, %1};" : "=l"(w2) : "f"(w));
        ulonglong2 xv = *reinterpret_cast<const ulonglong2*>(&Xs[k * 16 + g * 4]);
        fma2(acc01, xv.x, w2);
        fma2(acc23, xv.y, w2);
    }
    float a0, a1, a2, a3;
    asm("mov.b64 {%0, %1}, %2;" : "=f"(a0), "=f"(a1) : "l"(acc01));
    asm("mov.b64 {%0, %1}, %2;" : "=f"(a2), "=f"(a3) : "l"(acc23));
    int rb = row0 + g * 4;

    // ---- fp16 h store: pair (even c, odd c+1) — both lanes in the same warp ----
    float b0 = __shfl_down_sync(0xFFFFFFFFu, a0, 1);
    float b1 = __shfl_down_sync(0xFFFFFFFFu, a1, 1);
    float b2 = __shfl_down_sync(0xFFFFFFFFu, a2, 1);
    float b3 = __shfl_down_sync(0xFFFFFFFFu, a3, 1);
    if ((c & 1) == 0) {
        int cc = c >> 1;
        if (rb + 0 < N) g_h2[(rb + 0) * 32 + cc] = __floats2half2_rn(a0, b0);
        if (rb + 1 < N) g_h2[(rb + 1) * 32 + cc] = __floats2half2_rn(a1, b1);
        if (rb + 2 < N) g_h2[(rb + 2) * 32 + cc] = __floats2half2_rn(a2, b2);
        if (rb + 3 < N) g_h2[(rb + 3) * 32 + cc] = __floats2half2_rn(a3, b3);
    }

    // ---- fused alpha: as[row] = sum_c h[row][c]*a_src[c] (and a_dst) ----
    float asc = __ldg(&avs[c]), adc = __ldg(&avd[c]);
    float s0 = a0 * asc, s1 = a1 * asc, s2 = a2 * asc, s3 = a3 * asc;
    float d0 = a0 * adc, d1 = a1 * adc, d2 = a2 * adc, d3 = a3 * adc;
#pragma unroll
    for (int o = 16; o > 0; o >>= 1) {
        s0 += __shfl_down_sync(0xFFFFFFFFu, s0, o);
        s1 += __shfl_down_sync(0xFFFFFFFFu, s1, o);
        s2 += __shfl_down_sync(0xFFFFFFFFu, s2, o);
        s3 += __shfl_down_sync(0xFFFFFFFFu, s3, o);
        d0 += __shfl_down_sync(0xFFFFFFFFu, d0, o);
        d1 += __shfl_down_sync(0xFFFFFFFFu, d1, o);
        d2 += __shfl_down_sync(0xFFFFFFFFu, d2, o);
        d3 += __shfl_down_sync(0xFFFFFFFFu, d3, o);
    }
    if (lane == 0) {
        red[wid][0][0] = s0; red[wid][1][0] = s1; red[wid][2][0] = s2; red[wid][3][0] = s3;
        red[wid][0][1] = d0; red[wid][1][1] = d1; red[wid][2][1] = d2; red[wid][3][1] = d3;
    }
    __syncthreads();
    if (tid < 16) {
        int gg = tid >> 2, rr = tid & 3;
        int row = row0 + tid;
        if (row < N) {
            g_as[row] = red[2 * gg][rr][0] + red[2 * gg + 1][rr][0];
            g_ad[row] = red[2 * gg][rr][1] + red[2 * gg + 1][rr][1];
        }
    }
}

// ---------------- fused GAT aggregation: one warp per dst node ----------------------
// Shift-free softmax (scores O(1); fp32 exp cannot overflow). MLP-8 gather batching.
__global__ void k_gat(const float* __restrict__ bias, float* __restrict__ outbuf,
                      int do_relu, int N) {
    int warp = (blockIdx.x * blockDim.x + threadIdx.x) >> 5;
    int lane = threadIdx.x & 31;
    if (warp >= N) return;
    int beg = g_row[warp], end = g_row[warp + 1];
    float ad = g_ad[warp];
    const uint32_t* h2u = (const uint32_t*)g_h2;

    float accx = 0.f, accy = 0.f, ssum = 0.f;
    for (int base = beg; base < end; base += 32) {
        int i = base + lane;
        int srcl = 0;
        float p = 0.f;
        if (i < end) {
            srcl = g_ssrc[i];
            float e = g_as[srcl] + ad;
            e = (e > 0.f) ? e : 0.2f * e;      // LeakyReLU(0.2)
            p = __expf(e);
            ssum += p;
        }
        int cnt = min(32, end - base);
        for (int c0 = 0; c0 < cnt; c0 += 8) {
            uint32_t hw[8]; float pw[8];
#pragma unroll
            for (int j = 0; j < 8; j++) {
                int jj = c0 + j;
                float pv = __shfl_sync(0xFFFFFFFFu, p, jj & 31);
                int   sv = __shfl_sync(0xFFFFFFFFu, srcl, jj & 31);
                pw[j] = (jj < cnt) ? pv : 0.f;
                hw[j] = h2u[sv * 32 + lane];
            }
#pragma unroll
            for (int j = 0; j < 8; j++) {
                float2 hv = __half22float2(*reinterpret_cast<__half2*>(&hw[j]));
                accx += pw[j] * hv.x;
                accy += pw[j] * hv.y;
            }
        }
    }
#pragma unroll
    for (int o = 16; o > 0; o >>= 1)
        ssum += __shfl_xor_sync(0xFFFFFFFFu, ssum, o);

    float inv = 1.f / (ssum + 1e-16f);   // deg==0: acc=0 -> out=bias, matches ref
    float2 bv = ((const float2*)bias)[lane];
    float2 r;
    r.x = accx * inv + bv.x;
    r.y = accy * inv + bv.y;
    if (do_relu) { r.x = fmaxf(r.x, 0.f); r.y = fmaxf(r.y, 0.f); }
    ((float2*)outbuf)[warp * 32 + lane] = r;
}

// ---------------- launch -------------------------------------------------------------
extern "C" void kernel_launch(void* const* d_in, const int* in_sizes, int n_in,
                              void* d_out, int out_size) {
    // ---- size-driven role assignment (robust to metadata ordering) ----
    int ix = 0, ie = 0, iw1 = 0, iw2 = 0;
    for (int i = 1; i < n_in; i++) if (in_sizes[i] > in_sizes[ix]) ix = i;
    ie = (ix == 0) ? 1 : 0;
    for (int i = 0; i < n_in; i++) if (i != ix && in_sizes[i] > in_sizes[ie]) ie = i;
    iw1 = -1;
    for (int i = 0; i < n_in; i++) {
        if (i == ix || i == ie) continue;
        if (iw1 < 0 || in_sizes[i] > in_sizes[iw1]) iw1 = i;
    }
    iw2 = -1;
    for (int i = 0; i < n_in; i++) {
        if (i == ix || i == ie || i == iw1) continue;
        if (iw2 < 0 || in_sizes[i] > in_sizes[iw2]) iw2 = i;
    }
    int rv[6]; int nrv = 0;
    for (int i = 0; i < n_in && nrv < 6; i++)
        if (i != ix && i != ie && i != iw1 && i != iw2) rv[nrv++] = i;

    int ias1, iad1, ib1, ias2, iad2, ib2;
    if (ix == 0) {  // signature/dict order
        ias1 = rv[0]; iad1 = rv[1]; ib1 = rv[2];
        ias2 = rv[3]; iad2 = rv[4]; ib2 = rv[5];
    } else {        // alphabetical order
        iad1 = rv[0]; iad2 = rv[1]; ias1 = rv[2];
        ias2 = rv[3]; ib1  = rv[4]; ib2  = rv[5];
    }

    const float* x   = (const float*)d_in[ix];
    const void*  ei  = d_in[ie];
    const float* W1  = (const float*)d_in[iw1];
    const float* as1 = (const float*)d_in[ias1];
    const float* ad1 = (const float*)d_in[iad1];
    const float* b1  = (const float*)d_in[ib1];
    const float* W2  = (const float*)d_in[iw2];
    const float* as2 = (const float*)d_in[ias2];
    const float* ad2 = (const float*)d_in[iad2];
    const float* b2  = (const float*)d_in[ib2];
    float*       out = (float*)d_out;

    const int Hd  = in_sizes[ias1];         // 64
    const int Fin = in_sizes[iw1] / Hd;     // 128
    const int N   = in_sizes[ix] / Fin;     // 50000
    const int E   = in_sizes[ie] / 2;       // 800000

    float* p_x2 = nullptr;
    cudaGetSymbolAddress((void**)&p_x2, g_x2);

    const int B_E2   = (E / 2 + 255) / 256;
    const int B_E4   = (E / 4 + 1 + 255) / 256;
    const int B_NM4  = (NMAX / 4 + 255) / 256;
    const int B_WARP = (N * 32 + 255) / 256;
    const int B_ROWS = (N + 15) / 16;

    // Launch order chosen so the ncu window (4th launch) lands on k_gemm64<128>.
    k_zero<<<B_NM4, 256>>>();                              // 1
    k_ingest<<<B_E2, 256>>>(ei, E, N);                     // 2
    k_scan<<<1, 1024>>>();                                 // 3
    k_gemm64<128><<<B_ROWS, 256>>>(x, W1, as1, ad1, N);    // 4  <- profiled
    k_scatter<<<B_E4, 256>>>(E);                           // 5
    k_gat<<<B_WARP, 256>>>(b1, p_x2, 1, N);                // 6
    k_gemm64<64><<<B_ROWS, 256>>>(p_x2, W2, as2, ad2, N);  // 7
    k_gat<<<B_WARP, 256>>>(b2, out, 0, N);                 // 8
}

// round 9
// speedup vs baseline: 1.4601x; 1.4601x over previous
#include <cuda_runtime.h>
#include <cuda_fp16.h>
#include <cstdint>
#include <math_constants.h>

// Fixed dataset shape: N=50000, E=800000, Fin=128, H=C=64
#define NMAX 50048
#define EMAX 800000
#define HC   64

// ---------------- scratch (__device__ globals; no allocation allowed) --------------
__device__ __half2 g_h2[NMAX * 32];   // h = x @ W, fp16x2 (channel pairs)
__device__ float   g_x2[NMAX * HC];   // layer-2 input (fp32)
__device__ float   g_as[NMAX];        // alpha_src per node
__device__ float   g_ad[NMAX];        // alpha_dst per node
__device__ int     g_src[EMAX];       // edge src
__device__ int     g_dst[EMAX];       // edge dst
__device__ int     g_rank[EMAX];      // rank of edge within its dst row
__device__ int     g_deg[NMAX];       // in-degree histogram
__device__ int     g_row[NMAX + 4];   // CSR row starts (int4-padded)
__device__ int     g_ssrc[EMAX];      // src ids grouped by dst

// packed f32x2 fma (sm_103a; ptxas never emits FFMA2 from C++)
__device__ __forceinline__ void fma2(unsigned long long& acc,
                                     unsigned long long x2, unsigned long long w2) {
    asm("fma.rn.f32x2 %0, %1, %2, %0;" : "+l"(acc) : "l"(x2), "l"(w2));
}

// ---------------- ingest: dtype-detect + convert + histogram + rank -----------------
__global__ void k_zero() {
    int i = blockIdx.x * 256 + threadIdx.x;
    if (i < NMAX / 4) ((int4*)g_deg)[i] = make_int4(0, 0, 0, 0);
}

// 2 edges/thread. Dtype vote: read edge pair AS longlong2 (spans exactly the int32
// buffer bytes — safe both ways).
__global__ void k_ingest(const void* __restrict__ eiv, int E, int N) {
    int i = blockIdx.x * 256 + threadIdx.x;
    int e0 = i * 2;
    long long v0 = 0, v1 = 0;
    int ok = 1;
    if (e0 + 1 < E) {
        longlong2 v = ((const longlong2*)eiv)[i];
        v0 = v.x; v1 = v.y;
        ok = (v0 >= 0 && v0 < (long long)N && v1 >= 0 && v1 < (long long)N) ? 1 : 0;
    } else if (e0 < E) {
        v0 = ((const long long*)eiv)[e0];
        ok = (v0 >= 0 && v0 < (long long)N) ? 1 : 0;
    }
    int all64 = __syncthreads_and(ok);
    if (e0 >= E) return;
    int s0, s1 = 0, d0, d1 = 0;
    int has1 = (e0 + 1 < E);
    if (all64) {
        const long long* e = (const long long*)eiv;
        s0 = (int)v0;
        d0 = (int)e[E + e0];
        if (has1) { s1 = (int)v1; d1 = (int)e[E + e0 + 1]; }
    } else {
        const int* e = (const int*)eiv;
        s0 = e[e0];
        d0 = e[E + e0];
        if (has1) { s1 = e[e0 + 1]; d1 = e[E + e0 + 1]; }
    }
    s0 = min(max(s0, 0), N - 1); d0 = min(max(d0, 0), N - 1);
    g_src[e0] = s0; g_dst[e0] = d0;
    g_rank[e0] = atomicAdd(&g_deg[d0], 1);
    if (has1) {
        s1 = min(max(s1, 0), N - 1); d1 = min(max(d1, 0), N - 1);
        g_src[e0 + 1] = s1; g_dst[e0 + 1] = d1;
        g_rank[e0 + 1] = atomicAdd(&g_deg[d1], 1);
    }
}

// single-block exclusive scan over g_deg -> g_row; int4, 4096 elems/iteration
__global__ void k_scan() {
    __shared__ int warp_red[32];
    __shared__ int s_carry;
    int tid = threadIdx.x, lane = tid & 31, wid = tid >> 5;
    if (tid == 0) s_carry = 0;
    __syncthreads();
    const int4* deg4 = (const int4*)g_deg;
    int4*       row4 = (int4*)g_row;
    const int total4 = NMAX / 4;
    for (int base = 0; base < total4; base += 1024) {
        int idx = base + tid;
        int4 v = (idx < total4) ? deg4[idx] : make_int4(0, 0, 0, 0);
        int s = v.x + v.y + v.z + v.w;
        int x = s;
#pragma unroll
        for (int o = 1; o < 32; o <<= 1) {
            int t = __shfl_up_sync(0xFFFFFFFFu, x, o);
            if (lane >= o) x += t;
        }
        if (lane == 31) warp_red[wid] = x;
        __syncthreads();
        if (wid == 0) {
            int w = warp_red[lane];
#pragma unroll
            for (int o = 1; o < 32; o <<= 1) {
                int t = __shfl_up_sync(0xFFFFFFFFu, w, o);
                if (lane >= o) w += t;
            }
            warp_red[lane] = w;
        }
        __syncthreads();
        int wsum = (wid > 0) ? warp_red[wid - 1] : 0;
        int incl = x + wsum;
        int carry = s_carry;
        if (idx < total4) {
            int e0 = carry + incl - s;
            int4 r;
            r.x = e0;
            r.y = e0 + v.x;
            r.z = e0 + v.x + v.y;
            r.w = e0 + v.x + v.y + v.z;
            row4[idx] = r;
        }
        __syncthreads();
        if (tid == 1023) s_carry = carry + incl;
        __syncthreads();
    }
}

// atomic-free scatter, 4 edges/thread (int4 loads; MLP=4)
__global__ void k_scatter(int E) {
    int i = blockIdx.x * 256 + threadIdx.x;
    int nvec = E >> 2;
    if (i < nvec) {
        int4 d = ((const int4*)g_dst)[i];
        int4 r = ((const int4*)g_rank)[i];
        int4 s = ((const int4*)g_src)[i];
        int b0 = g_row[d.x], b1 = g_row[d.y], b2 = g_row[d.z], b3 = g_row[d.w];
        g_ssrc[b0 + r.x] = s.x;
        g_ssrc[b1 + r.y] = s.y;
        g_ssrc[b2 + r.z] = s.z;
        g_ssrc[b3 + r.w] = s.w;
    } else if (i == nvec) {
        for (int e = nvec * 4; e < E; e++)
            g_ssrc[g_row[g_dst[e]] + g_rank[e]] = g_src[e];
    }
}

// ---------------- register-blocked GEMM + fused alpha + fp16 h store -----------------
// H[N,64] = X[N,K] @ W[K,64].  BM=128 rows, BN=64 cols, KT=32 k-tile, 256 threads.
// Thread (tx=tid%16, ty=tid/16) owns an 8-row x 4-col register tile:
//   rows row0 + ty*8 .. +7, cols tx*4 .. +3.
// Per k: 2 LDS.128 (X frag, 2-way broadcast) + 1 LDS.128 (W frag) -> 16 FFMA2.
template <int K>
__launch_bounds__(256)
__global__ void k_gemm64(const float* __restrict__ X, const float* __restrict__ W,
                         const float* __restrict__ avs, const float* __restrict__ avd,
                         int N) {
    const int XS_STRIDE = 132;            // 128 + 4 pad (keeps float4 alignment)
    __shared__ float Xs[32 * XS_STRIDE];  // Xs[k][row], transposed
    __shared__ float Ws[32 * 64];         // Ws[k][col]
    int tid = threadIdx.x;
    int tx = tid & 15, ty = tid >> 4;
    int row0 = blockIdx.x * 128;

    unsigned long long acc[4][4];         // [row-pair][col], packed f32x2
#pragma unroll
    for (int rp = 0; rp < 4; rp++)
#pragma unroll
        for (int c = 0; c < 4; c++) acc[rp][c] = 0ull;

    for (int k0 = 0; k0 < K; k0 += 32) {
        // X tile: 128 rows x 32 k. 8 threads/row (float4 along k), 32 rows/pass.
        int kq = tid & 7;
        int rbase = tid >> 3;
#pragma unroll
        for (int pass = 0; pass < 4; pass++) {
            int row_l = rbase + pass * 32;
            int row = row0 + row_l;
            float4 v = make_float4(0.f, 0.f, 0.f, 0.f);
            if (row < N) v = *reinterpret_cast<const float4*>(&X[row * K + k0 + kq * 4]);
            Xs[(kq * 4 + 0) * XS_STRIDE + row_l] = v.x;
            Xs[(kq * 4 + 1) * XS_STRIDE + row_l] = v.y;
            Xs[(kq * 4 + 2) * XS_STRIDE + row_l] = v.z;
            Xs[(kq * 4 + 3) * XS_STRIDE + row_l] = v.w;
        }
        // W tile: 32 k x 64 cols = 512 float4, 2 per thread.
#pragma unroll
        for (int j = 0; j < 2; j++) {
            int f = tid + j * 256;
            int k_l = f >> 4, cq = f & 15;
            *reinterpret_cast<float4*>(&Ws[k_l * 64 + cq * 4]) =
                *reinterpret_cast<const float4*>(&W[(k0 + k_l) * 64 + cq * 4]);
        }
        __syncthreads();

#pragma unroll
        for (int k = 0; k < 32; k++) {
            ulonglong2 xa = *reinterpret_cast<const ulonglong2*>(&Xs[k * XS_STRIDE + ty * 8]);
            ulonglong2 xb = *reinterpret_cast<const ulonglong2*>(&Xs[k * XS_STRIDE + ty * 8 + 4]);
            float4 wv = *reinterpret_cast<const float4*>(&Ws[k * 64 + tx * 4]);
            unsigned long long w2[4];
            asm("mov.b64 %0, {%1, %1};" : "=l"(w2[0]) : "f"(wv.x));
            asm("mov.b64 %0, {%1, %1};" : "=l"(w2[1]) : "f"(wv.y));
            asm("mov.b64 %0, {%1, %1};" : "=l"(w2[2]) : "f"(wv.z));
            asm("mov.b64 %0, {%1, %1};" : "=l"(w2[3]) : "f"(wv.w));
#pragma unroll
            for (int c = 0; c < 4; c++) {
                fma2(acc[0][c], xa.x, w2[c]);
                fma2(acc[1][c], xa.y, w2[c]);
                fma2(acc[2][c], xb.x, w2[c]);
                fma2(acc[3][c], xb.y, w2[c]);
            }
        }
        __syncthreads();
    }

    // unpack accumulators: a[i][j] = H[row0+ty*8+i][tx*4+j]
    float a[8][4];
#pragma unroll
    for (int rp = 0; rp < 4; rp++)
#pragma unroll
        for (int c = 0; c < 4; c++) {
            float lo, hi;
            asm("mov.b64 {%0, %1}, %2;" : "=f"(lo), "=f"(hi) : "l"(acc[rp][c]));
            a[rp * 2 + 0][c] = lo;
            a[rp * 2 + 1][c] = hi;
        }

    // fused alpha dot products (width-16 shfl reduce across the 16 col-threads)
    float avs4[4], avd4[4];
#pragma unroll
    for (int j = 0; j < 4; j++) {
        avs4[j] = __ldg(&avs[tx * 4 + j]);
        avd4[j] = __ldg(&avd[tx * 4 + j]);
    }
#pragma unroll
    for (int i = 0; i < 8; i++) {
        int row = row0 + ty * 8 + i;
        float s = a[i][0] * avs4[0] + a[i][1] * avs4[1] + a[i][2] * avs4[2] + a[i][3] * avs4[3];
        float d = a[i][0] * avd4[0] + a[i][1] * avd4[1] + a[i][2] * avd4[2] + a[i][3] * avd4[3];
#pragma unroll
        for (int o = 8; o > 0; o >>= 1) {
            s += __shfl_down_sync(0xFFFFFFFFu, s, o, 16);
            d += __shfl_down_sync(0xFFFFFFFFu, d, o, 16);
        }
        if (tx == 0 && row < N) { g_as[row] = s; g_ad[row] = d; }
        // fp16 h store: 2 half2 = one 8-byte store
        if (row < N) {
            __half2 h01 = __floats2half2_rn(a[i][0], a[i][1]);
            __half2 h23 = __floats2half2_rn(a[i][2], a[i][3]);
            uint2 pk = make_uint2(*reinterpret_cast<uint32_t*>(&h01),
                                  *reinterpret_cast<uint32_t*>(&h23));
            *reinterpret_cast<uint2*>(&g_h2[row * 32 + tx * 2]) = pk;
        }
    }
}

// ---------------- fused GAT aggregation: one warp per dst node ----------------------
// Shift-free softmax (scores O(1); fp32 exp cannot overflow). MLP-8 gather batching.
__global__ void k_gat(const float* __restrict__ bias, float* __restrict__ outbuf,
                      int do_relu, int N) {
    int warp = (blockIdx.x * blockDim.x + threadIdx.x) >> 5;
    int lane = threadIdx.x & 31;
    if (warp >= N) return;
    int beg = g_row[warp], end = g_row[warp + 1];
    float ad = g_ad[warp];
    const uint32_t* h2u = (const uint32_t*)g_h2;

    float accx = 0.f, accy = 0.f, ssum = 0.f;
    for (int base = beg; base < end; base += 32) {
        int i = base + lane;
        int srcl = 0;
        float p = 0.f;
        if (i < end) {
            srcl = g_ssrc[i];
            float e = g_as[srcl] + ad;
            e = (e > 0.f) ? e : 0.2f * e;      // LeakyReLU(0.2)
            p = __expf(e);
            ssum += p;
        }
        int cnt = min(32, end - base);
        for (int c0 = 0; c0 < cnt; c0 += 8) {
            uint32_t hw[8]; float pw[8];
#pragma unroll
            for (int j = 0; j < 8; j++) {
                int jj = c0 + j;
                float pv = __shfl_sync(0xFFFFFFFFu, p, jj & 31);
                int   sv = __shfl_sync(0xFFFFFFFFu, srcl, jj & 31);
                pw[j] = (jj < cnt) ? pv : 0.f;
                hw[j] = h2u[sv * 32 + lane];
            }
#pragma unroll
            for (int j = 0; j < 8; j++) {
                float2 hv = __half22float2(*reinterpret_cast<__half2*>(&hw[j]));
                accx += pw[j] * hv.x;
                accy += pw[j] * hv.y;
            }
        }
    }
#pragma unroll
    for (int o = 16; o > 0; o >>= 1)
        ssum += __shfl_xor_sync(0xFFFFFFFFu, ssum, o);

    float inv = 1.f / (ssum + 1e-16f);   // deg==0: acc=0 -> out=bias, matches ref
    float2 bv = ((const float2*)bias)[lane];
    float2 r;
    r.x = accx * inv + bv.x;
    r.y = accy * inv + bv.y;
    if (do_relu) { r.x = fmaxf(r.x, 0.f); r.y = fmaxf(r.y, 0.f); }
    ((float2*)outbuf)[warp * 32 + lane] = r;
}

// ---------------- launch -------------------------------------------------------------
extern "C" void kernel_launch(void* const* d_in, const int* in_sizes, int n_in,
                              void* d_out, int out_size) {
    // ---- size-driven role assignment (robust to metadata ordering) ----
    int ix = 0, ie = 0, iw1 = 0, iw2 = 0;
    for (int i = 1; i < n_in; i++) if (in_sizes[i] > in_sizes[ix]) ix = i;
    ie = (ix == 0) ? 1 : 0;
    for (int i = 0; i < n_in; i++) if (i != ix && in_sizes[i] > in_sizes[ie]) ie = i;
    iw1 = -1;
    for (int i = 0; i < n_in; i++) {
        if (i == ix || i == ie) continue;
        if (iw1 < 0 || in_sizes[i] > in_sizes[iw1]) iw1 = i;
    }
    iw2 = -1;
    for (int i = 0; i < n_in; i++) {
        if (i == ix || i == ie || i == iw1) continue;
        if (iw2 < 0 || in_sizes[i] > in_sizes[iw2]) iw2 = i;
    }
    int rv[6]; int nrv = 0;
    for (int i = 0; i < n_in && nrv < 6; i++)
        if (i != ix && i != ie && i != iw1 && i != iw2) rv[nrv++] = i;

    int ias1, iad1, ib1, ias2, iad2, ib2;
    if (ix == 0) {  // signature/dict order
        ias1 = rv[0]; iad1 = rv[1]; ib1 = rv[2];
        ias2 = rv[3]; iad2 = rv[4]; ib2 = rv[5];
    } else {        // alphabetical order
        iad1 = rv[0]; iad2 = rv[1]; ias1 = rv[2];
        ias2 = rv[3]; ib1  = rv[4]; ib2  = rv[5];
    }

    const float* x   = (const float*)d_in[ix];
    const void*  ei  = d_in[ie];
    const float* W1  = (const float*)d_in[iw1];
    const float* as1 = (const float*)d_in[ias1];
    const float* ad1 = (const float*)d_in[iad1];
    const float* b1  = (const float*)d_in[ib1];
    const float* W2  = (const float*)d_in[iw2];
    const float* as2 = (const float*)d_in[ias2];
    const float* ad2 = (const float*)d_in[iad2];
    const float* b2  = (const float*)d_in[ib2];
    float*       out = (float*)d_out;

    const int Hd  = in_sizes[ias1];         // 64
    const int Fin = in_sizes[iw1] / Hd;     // 128
    const int N   = in_sizes[ix] / Fin;     // 50000
    const int E   = in_sizes[ie] / 2;       // 800000

    float* p_x2 = nullptr;
    cudaGetSymbolAddress((void**)&p_x2, g_x2);

    const int B_E2   = (E / 2 + 255) / 256;
    const int B_E4   = (E / 4 + 1 + 255) / 256;
    const int B_NM4  = (NMAX / 4 + 255) / 256;
    const int B_WARP = (N * 32 + 255) / 256;
    const int B_GEMM = (N + 127) / 128;

    // Launch order keeps ncu window (4th launch) on k_gemm64<128> to verify the fix.
    k_zero<<<B_NM4, 256>>>();                              // 1
    k_ingest<<<B_E2, 256>>>(ei, E, N);                     // 2
    k_scan<<<1, 1024>>>();                                 // 3
    k_gemm64<128><<<B_GEMM, 256>>>(x, W1, as1, ad1, N);    // 4  <- profiled
    k_scatter<<<B_E4, 256>>>(E);                           // 5
    k_gat<<<B_WARP, 256>>>(b1, p_x2, 1, N);                // 6
    k_gemm64<64><<<B_GEMM, 256>>>(p_x2, W2, as2, ad2, N);  // 7
    k_gat<<<B_WARP, 256>>>(b2, out, 0, N);                 // 8
}